// round 14
// baseline (speedup 1.0000x reference)
#include <cuda_runtime.h>
#include <cuda_fp16.h>
#include <cstdint>

// ---------------------------------------------------------------------------
// BitLinear 1.58b on sm_103 (baseline PTX only — no tcgen05 / 'a' features):
//   y[m,o] = s_w[o] * sum_k z[m,k] * t[o,k]
//   z = absmax fake-quant of x (fp16), t = ternary weights {-1,0,1} (fp16)
// r11 quant kernels (validated) -> r12 GEMM structure with ONE change:
// 6-stage cp.async ring, TWO k-tiles per barrier (halves sync/wait overhead;
// measured r12: tensor pipe 76%, ~176 cyc/k-tile of barrier overhead).
// ---------------------------------------------------------------------------

static constexpr int M_TOT = 8192;
static constexpr int K_TOT = 4096;
static constexpr int N_TOT = 4096;

static constexpr int TILE_M = 128;
static constexpr int TILE_N = 256;
static constexpr int TILE_K = 32;
static constexpr int NK     = K_TOT / TILE_K;   // 128
static constexpr int STAGES = 6;                // ring depth (pairs consume 2)

static constexpr int A_STAGE = TILE_M * TILE_K * 2;      // 8192 B
static constexpr int B_STAGE = TILE_N * TILE_K * 2;      // 16384 B
static constexpr int STAGE_BYTES = A_STAGE + B_STAGE;    // 24576 B
static constexpr int SMEM_DYN = STAGES * STAGE_BYTES;    // 147456 B

// scratch: quantized operands (module-scope device memory, no allocs)
__device__ __align__(16) __half g_z [(size_t)M_TOT * K_TOT];   // 64 MB
__device__ __align__(16) __half g_wt[(size_t)N_TOT * K_TOT];   // 32 MB
__device__ float g_sw[N_TOT];

// ---------------------------------------------------------------------------
// PTX helpers (all baseline sm_80/sm_90 features)
// ---------------------------------------------------------------------------
__device__ __forceinline__ uint32_t smem_u32(const void* p) {
    uint32_t a;
    asm("{ .reg .u64 t; cvta.to.shared.u64 t, %1; cvt.u32.u64 %0, t; }" : "=r"(a) : "l"(p));
    return a;
}
__device__ __forceinline__ void cp_async16(uint32_t saddr, const void* g) {
    asm volatile("cp.async.cg.shared.global [%0], [%1], 16;" :: "r"(saddr), "l"(g) : "memory");
}
__device__ __forceinline__ void cp_commit() {
    asm volatile("cp.async.commit_group;" ::: "memory");
}
template<int N> __device__ __forceinline__ void cp_wait() {
    asm volatile("cp.async.wait_group %0;" :: "n"(N) : "memory");
}
__device__ __forceinline__ void ldsm4(uint32_t* r, uint32_t addr) {
    asm volatile("ldmatrix.sync.aligned.m8n8.x4.shared.b16 {%0,%1,%2,%3}, [%4];"
                 : "=r"(r[0]), "=r"(r[1]), "=r"(r[2]), "=r"(r[3]) : "r"(addr));
}
__device__ __forceinline__ void mma16816(float* c, const uint32_t* a, uint32_t b0, uint32_t b1) {
    asm volatile(
        "mma.sync.aligned.m16n8k16.row.col.f32.f16.f16.f32 "
        "{%0,%1,%2,%3}, {%4,%5,%6,%7}, {%8,%9}, {%0,%1,%2,%3};"
        : "+f"(c[0]), "+f"(c[1]), "+f"(c[2]), "+f"(c[3])
        : "r"(a[0]), "r"(a[1]), "r"(a[2]), "r"(a[3]), "r"(b0), "r"(b1));
}

// ---------------------------------------------------------------------------
// quantize x: per-token groups of 64, absmax fake-quant -> fp16 row-major
// (r11 verbatim)
// ---------------------------------------------------------------------------
__global__ void __launch_bounds__(256) quant_x_kernel(const float* __restrict__ x) {
    const int m = blockIdx.x;
    const int t = threadIdx.x;

    const float4* xp = reinterpret_cast<const float4*>(x + (size_t)m * K_TOT + t * 16);
    float v[16];
#pragma unroll
    for (int i = 0; i < 4; ++i) {
        float4 f = xp[i];
        v[4*i+0] = f.x; v[4*i+1] = f.y; v[4*i+2] = f.z; v[4*i+3] = f.w;
    }

    float am = 0.f;
#pragma unroll
    for (int i = 0; i < 16; ++i) am = fmaxf(am, fabsf(v[i]));
    am = fmaxf(am, __shfl_xor_sync(0xffffffffu, am, 1));
    am = fmaxf(am, __shfl_xor_sync(0xffffffffu, am, 2));
    am = fmaxf(am, 1e-5f);
    const float scale = 127.0f / am;
    const float inv   = am * (1.0f / 127.0f);

    uint32_t p[8];
#pragma unroll
    for (int i = 0; i < 8; ++i) {
        float q0 = fminf(fmaxf(rintf(v[2*i+0] * scale), -127.f), 127.f) * inv;
        float q1 = fminf(fmaxf(rintf(v[2*i+1] * scale), -127.f), 127.f) * inv;
        __half2 h = __floats2half2_rn(q0, q1);
        p[i] = *reinterpret_cast<uint32_t*>(&h);
    }

    uint4* dst = reinterpret_cast<uint4*>(g_z + (size_t)m * K_TOT + t * 16);
    dst[0] = make_uint4(p[0], p[1], p[2], p[3]);
    dst[1] = make_uint4(p[4], p[5], p[6], p[7]);
}

// ---------------------------------------------------------------------------
// quantize w: per-row absmean ternary -> fp16 {-1,0,1}; s_w fp32 (r11 verbatim)
// ---------------------------------------------------------------------------
__global__ void __launch_bounds__(256) quant_w_kernel(const float* __restrict__ w) {
    __shared__ float red[8];
    __shared__ float s_sh;
    const int o = blockIdx.x;
    const int t = threadIdx.x;

    const float4* wp = reinterpret_cast<const float4*>(w + (size_t)o * K_TOT + t * 16);
    float v[16];
#pragma unroll
    for (int i = 0; i < 4; ++i) {
        float4 f = wp[i];
        v[4*i+0] = f.x; v[4*i+1] = f.y; v[4*i+2] = f.z; v[4*i+3] = f.w;
    }

    float acc = 0.f;
#pragma unroll
    for (int i = 0; i < 16; ++i) acc += fabsf(v[i]);
#pragma unroll
    for (int d = 16; d > 0; d >>= 1) acc += __shfl_xor_sync(0xffffffffu, acc, d);
    if ((t & 31) == 0) red[t >> 5] = acc;
    __syncthreads();
    if (t == 0) {
        float tot = 0.f;
#pragma unroll
        for (int i = 0; i < 8; ++i) tot += red[i];
        float s = fmaxf(tot * (1.0f / 4096.0f), 1e-5f);
        s_sh = s;
        g_sw[o] = s;
    }
    __syncthreads();
    const float inv_s = 1.0f / s_sh;

    uint32_t p[8];
#pragma unroll
    for (int i = 0; i < 8; ++i) {
        float t0 = fminf(fmaxf(rintf(v[2*i+0] * inv_s), -1.f), 1.f);
        float t1 = fminf(fmaxf(rintf(v[2*i+1] * inv_s), -1.f), 1.f);
        __half2 h = __floats2half2_rn(t0, t1);
        p[i] = *reinterpret_cast<uint32_t*>(&h);
    }

    uint4* dst = reinterpret_cast<uint4*>(g_wt + (size_t)o * K_TOT + t * 16);
    dst[0] = make_uint4(p[0], p[1], p[2], p[3]);
    dst[1] = make_uint4(p[4], p[5], p[6], p[7]);
}

// ---------------------------------------------------------------------------
// GEMM: 128M x 256N per CTA, K-step 32, 6-stage cp.async ring, mma.sync.
// 8 warps (2M x 4N), each 64x64 (r12's validated decomposition).
// TWO k-tiles per barrier: pair (kp,kp+1) waits cp_wait<2>, computes both
// stages, then prefetches kp+4 -> stage (kp-2)%6 and kp+5 -> stage (kp-1)%6
// (both consumed in the PREVIOUS pair; this pair's syncthreads guards reuse).
// smem swizzle: within a 64B row (4 x 16B chunks), phys_chunk = c ^ ((row>>1)&3)
// ---------------------------------------------------------------------------
__global__ void __launch_bounds__(256, 1) bitlinear_gemm(float* __restrict__ out) {
    extern __shared__ __align__(128) unsigned char smem[];
    __shared__ float s_sw[TILE_N];
    const uint32_t sb = smem_u32(smem);
    const int tid  = threadIdx.x;
    const int lane = tid & 31;
    const int wid  = tid >> 5;
    const int nt = blockIdx.x;   // 0..15
    const int mt = blockIdx.y;   // 0..63
    const int warp_m = (wid & 1) * 64;
    const int warp_n = (wid >> 1) * 64;

    s_sw[tid] = g_sw[nt * TILE_N + tid];

    const __half* gA = g_z  + (size_t)(mt * TILE_M) * K_TOT;
    const __half* gB = g_wt + (size_t)(nt * TILE_N) * K_TOT;

    // --- loader task precompute (A: 512 x 16B chunks, B: 1024) ---
    uint32_t a_sm[2]; const __half* a_gm[2];
#pragma unroll
    for (int i = 0; i < 2; ++i) {
        int idx = tid + 256 * i, r = idx >> 2, c = idx & 3;
        a_sm[i] = r * 64 + ((c ^ ((r >> 1) & 3)) * 16);
        a_gm[i] = gA + (size_t)r * K_TOT + c * 8;
    }
    uint32_t b_sm[4]; const __half* b_gm[4];
#pragma unroll
    for (int i = 0; i < 4; ++i) {
        int idx = tid + 256 * i, r = idx >> 2, c = idx & 3;
        b_sm[i] = A_STAGE + r * 64 + ((c ^ ((r >> 1) & 3)) * 16);
        b_gm[i] = gB + (size_t)r * K_TOT + c * 8;
    }

    // --- ldmatrix lane address offsets (kk=0); kk=1 -> XOR 32 ---
    const int rA = warp_m + (lane & 15);
    const uint32_t aoff = rA * 64 + ((((lane >> 4) & 1) ^ ((rA >> 1) & 3)) * 16);
    const int rB = warp_n + (lane & 7) + ((lane >> 4) << 3);
    const uint32_t boff = A_STAGE + rB * 64 + ((((lane >> 3) & 1) ^ ((rB >> 1) & 3)) * 16);

    float acc[4][8][4];
#pragma unroll
    for (int i = 0; i < 4; ++i)
#pragma unroll
        for (int j = 0; j < 8; ++j)
#pragma unroll
            for (int e = 0; e < 4; ++e) acc[i][j][e] = 0.f;

    // prologue: prefetch 4 k-tiles (stages 0..3), one commit group each
#pragma unroll
    for (int s = 0; s < 4; ++s) {
        uint32_t base = sb + s * STAGE_BYTES;
#pragma unroll
        for (int i = 0; i < 2; ++i) cp_async16(base + a_sm[i], a_gm[i] + s * TILE_K);
#pragma unroll
        for (int i = 0; i < 4; ++i) cp_async16(base + b_sm[i], b_gm[i] + s * TILE_K);
        cp_commit();
    }

    for (int kp = 0; kp < NK; kp += 2) {
        cp_wait<2>();          // tiles kp and kp+1 resident (<=2 newest pending)
        __syncthreads();       // also guards reuse of stages (kp-2)%6, (kp-1)%6

        // ---- compute k-tile kp ----
        {
            const uint32_t sbase = sb + (kp % STAGES) * STAGE_BYTES;
#pragma unroll
            for (int kk = 0; kk < 2; ++kk) {
                const uint32_t kx = kk << 5;
                uint32_t a[4][4], b[4][4];
#pragma unroll
                for (int i = 0; i < 4; ++i) ldsm4(a[i], (sbase + aoff + i * 1024) ^ kx);
#pragma unroll
                for (int j = 0; j < 4; ++j) ldsm4(b[j], (sbase + boff + j * 1024) ^ kx);
#pragma unroll
                for (int i = 0; i < 4; ++i)
#pragma unroll
                    for (int j = 0; j < 8; ++j) {
                        const uint32_t* bt = b[j >> 1];
                        mma16816(acc[i][j], a[i], bt[(j & 1) * 2], bt[(j & 1) * 2 + 1]);
                    }
            }
        }
        // ---- compute k-tile kp+1 ----
        {
            const uint32_t sbase = sb + ((kp + 1) % STAGES) * STAGE_BYTES;
#pragma unroll
            for (int kk = 0; kk < 2; ++kk) {
                const uint32_t kx = kk << 5;
                uint32_t a[4][4], b[4][4];
#pragma unroll
                for (int i = 0; i < 4; ++i) ldsm4(a[i], (sbase + aoff + i * 1024) ^ kx);
#pragma unroll
                for (int j = 0; j < 4; ++j) ldsm4(b[j], (sbase + boff + j * 1024) ^ kx);
#pragma unroll
                for (int i = 0; i < 4; ++i)
#pragma unroll
                    for (int j = 0; j < 8; ++j) {
                        const uint32_t* bt = b[j >> 1];
                        mma16816(acc[i][j], a[i], bt[(j & 1) * 2], bt[(j & 1) * 2 + 1]);
                    }
            }
        }

        // ---- prefetch k-tiles kp+4, kp+5 (r2's known-good position) ----
        if (kp + 4 < NK) {
            const int kn = kp + 4;
            uint32_t base = sb + (kn % STAGES) * STAGE_BYTES;
#pragma unroll
            for (int i = 0; i < 2; ++i) cp_async16(base + a_sm[i], a_gm[i] + kn * TILE_K);
#pragma unroll
            for (int i = 0; i < 4; ++i) cp_async16(base + b_sm[i], b_gm[i] + kn * TILE_K);
        }
        cp_commit();
        if (kp + 5 < NK) {
            const int kn = kp + 5;
            uint32_t base = sb + (kn % STAGES) * STAGE_BYTES;
#pragma unroll
            for (int i = 0; i < 2; ++i) cp_async16(base + a_sm[i], a_gm[i] + kn * TILE_K);
#pragma unroll
            for (int i = 0; i < 4; ++i) cp_async16(base + b_sm[i], b_gm[i] + kn * TILE_K);
        }
        cp_commit();
    }

    // --- epilogue: scale by s_w[n], write fp32 ---
#pragma unroll
    for (int i = 0; i < 4; ++i) {
        const int r0 = mt * TILE_M + warp_m + i * 16 + (lane >> 2);
        float* o0 = out + (size_t)r0 * N_TOT + nt * TILE_N;
        float* o1 = o0 + 8 * N_TOT;
#pragma unroll
        for (int j = 0; j < 8; ++j) {
            const int col = warp_n + j * 8 + (lane & 3) * 2;
            const float sw0 = s_sw[col], sw1 = s_sw[col + 1];
            float2 v0 = make_float2(acc[i][j][0] * sw0, acc[i][j][1] * sw1);
            float2 v1 = make_float2(acc[i][j][2] * sw0, acc[i][j][3] * sw1);
            *reinterpret_cast<float2*>(o0 + col) = v0;
            *reinterpret_cast<float2*>(o1 + col) = v1;
        }
    }
}

// ---------------------------------------------------------------------------
// launch
// ---------------------------------------------------------------------------
extern "C" void kernel_launch(void* const* d_in, const int* in_sizes, int n_in,
                              void* d_out, int out_size) {
    (void)in_sizes; (void)n_in; (void)out_size;
    const float* x = (const float*)d_in[0];   // [4,2048,4096] fp32
    const float* w = (const float*)d_in[1];   // [4096,4096]   fp32
    float* out = (float*)d_out;               // [4,2048,4096] fp32

    quant_x_kernel<<<M_TOT, 256>>>(x);
    quant_w_kernel<<<N_TOT, 256>>>(w);

    static bool attr_set = false;
    if (!attr_set) {
        cudaFuncSetAttribute(bitlinear_gemm,
                             cudaFuncAttributeMaxDynamicSharedMemorySize, SMEM_DYN);
        attr_set = true;
    }
    dim3 grid(N_TOT / TILE_N, M_TOT / TILE_M);   // (16, 64)
    bitlinear_gemm<<<grid, 256, SMEM_DYN>>>(out);
}

// round 15
// speedup vs baseline: 1.1166x; 1.1166x over previous
#include <cuda_runtime.h>
#include <cuda_fp16.h>
#include <cstdint>

// ---------------------------------------------------------------------------
// BitLinear 1.58b on sm_103 (baseline PTX only — no tcgen05 / 'a' features):
//   y[m,o] = s_w[o] * sum_k z[m,k] * t[o,k]
//   z = absmax fake-quant of x (fp16), t = ternary weights {-1,0,1} (fp16)
// r11 (641.8us validated) byte-identical EXCEPT: epilogue stores use __stcs
// (evict-first) so the 128MB write-once output stream doesn't displace the
// L2-resident A/B working set. Single isolated variable.
// ---------------------------------------------------------------------------

static constexpr int M_TOT = 8192;
static constexpr int K_TOT = 4096;
static constexpr int N_TOT = 4096;

static constexpr int TILE_M = 128;
static constexpr int TILE_N = 256;
static constexpr int TILE_K = 32;
static constexpr int NK     = K_TOT / TILE_K;   // 128
static constexpr int STAGES = 4;

static constexpr int A_STAGE = TILE_M * TILE_K * 2;      // 8192 B
static constexpr int B_STAGE = TILE_N * TILE_K * 2;      // 16384 B
static constexpr int STAGE_BYTES = A_STAGE + B_STAGE;    // 24576 B
static constexpr int SMEM_DYN = STAGES * STAGE_BYTES;    // 98304 B

// scratch: quantized operands (module-scope device memory, no allocs)
__device__ __align__(16) __half g_z [(size_t)M_TOT * K_TOT];   // 64 MB
__device__ __align__(16) __half g_wt[(size_t)N_TOT * K_TOT];   // 32 MB
__device__ float g_sw[N_TOT];

// ---------------------------------------------------------------------------
// PTX helpers (all baseline sm_80/sm_90 features)
// ---------------------------------------------------------------------------
__device__ __forceinline__ uint32_t smem_u32(const void* p) {
    uint32_t a;
    asm("{ .reg .u64 t; cvta.to.shared.u64 t, %1; cvt.u32.u64 %0, t; }" : "=r"(a) : "l"(p));
    return a;
}
__device__ __forceinline__ void cp_async16(uint32_t saddr, const void* g) {
    asm volatile("cp.async.cg.shared.global [%0], [%1], 16;" :: "r"(saddr), "l"(g) : "memory");
}
__device__ __forceinline__ void cp_commit() {
    asm volatile("cp.async.commit_group;" ::: "memory");
}
template<int N> __device__ __forceinline__ void cp_wait() {
    asm volatile("cp.async.wait_group %0;" :: "n"(N) : "memory");
}
__device__ __forceinline__ void ldsm4(uint32_t* r, uint32_t addr) {
    asm volatile("ldmatrix.sync.aligned.m8n8.x4.shared.b16 {%0,%1,%2,%3}, [%4];"
                 : "=r"(r[0]), "=r"(r[1]), "=r"(r[2]), "=r"(r[3]) : "r"(addr));
}
__device__ __forceinline__ void mma16816(float* c, const uint32_t* a, uint32_t b0, uint32_t b1) {
    asm volatile(
        "mma.sync.aligned.m16n8k16.row.col.f32.f16.f16.f32 "
        "{%0,%1,%2,%3}, {%4,%5,%6,%7}, {%8,%9}, {%0,%1,%2,%3};"
        : "+f"(c[0]), "+f"(c[1]), "+f"(c[2]), "+f"(c[3])
        : "r"(a[0]), "r"(a[1]), "r"(a[2]), "r"(a[3]), "r"(b0), "r"(b1));
}

// ---------------------------------------------------------------------------
// quantize x: per-token groups of 64, absmax fake-quant -> fp16 row-major
// grid = 8192 blocks x 256 threads; thread t handles 16 contiguous k
// ---------------------------------------------------------------------------
__global__ void __launch_bounds__(256) quant_x_kernel(const float* __restrict__ x) {
    const int m = blockIdx.x;
    const int t = threadIdx.x;

    const float4* xp = reinterpret_cast<const float4*>(x + (size_t)m * K_TOT + t * 16);
    float v[16];
#pragma unroll
    for (int i = 0; i < 4; ++i) {
        float4 f = xp[i];
        v[4*i+0] = f.x; v[4*i+1] = f.y; v[4*i+2] = f.z; v[4*i+3] = f.w;
    }

    float am = 0.f;
#pragma unroll
    for (int i = 0; i < 16; ++i) am = fmaxf(am, fabsf(v[i]));
    // group of 64 elems = 4 consecutive lanes (quad-aligned)
    am = fmaxf(am, __shfl_xor_sync(0xffffffffu, am, 1));
    am = fmaxf(am, __shfl_xor_sync(0xffffffffu, am, 2));
    am = fmaxf(am, 1e-5f);
    const float scale = 127.0f / am;
    const float inv   = am * (1.0f / 127.0f);

    uint32_t p[8];
#pragma unroll
    for (int i = 0; i < 8; ++i) {
        float q0 = fminf(fmaxf(rintf(v[2*i+0] * scale), -127.f), 127.f) * inv;
        float q1 = fminf(fmaxf(rintf(v[2*i+1] * scale), -127.f), 127.f) * inv;
        __half2 h = __floats2half2_rn(q0, q1);
        p[i] = *reinterpret_cast<uint32_t*>(&h);
    }

    uint4* dst = reinterpret_cast<uint4*>(g_z + (size_t)m * K_TOT + t * 16);
    dst[0] = make_uint4(p[0], p[1], p[2], p[3]);
    dst[1] = make_uint4(p[4], p[5], p[6], p[7]);
}

// ---------------------------------------------------------------------------
// quantize w: per-row absmean ternary -> fp16 {-1,0,1} row-major; s_w fp32
// ---------------------------------------------------------------------------
__global__ void __launch_bounds__(256) quant_w_kernel(const float* __restrict__ w) {
    __shared__ float red[8];
    __shared__ float s_sh;
    const int o = blockIdx.x;
    const int t = threadIdx.x;

    const float4* wp = reinterpret_cast<const float4*>(w + (size_t)o * K_TOT + t * 16);
    float v[16];
#pragma unroll
    for (int i = 0; i < 4; ++i) {
        float4 f = wp[i];
        v[4*i+0] = f.x; v[4*i+1] = f.y; v[4*i+2] = f.z; v[4*i+3] = f.w;
    }

    float acc = 0.f;
#pragma unroll
    for (int i = 0; i < 16; ++i) acc += fabsf(v[i]);
#pragma unroll
    for (int d = 16; d > 0; d >>= 1) acc += __shfl_xor_sync(0xffffffffu, acc, d);
    if ((t & 31) == 0) red[t >> 5] = acc;
    __syncthreads();
    if (t == 0) {
        float tot = 0.f;
#pragma unroll
        for (int i = 0; i < 8; ++i) tot += red[i];
        float s = fmaxf(tot * (1.0f / 4096.0f), 1e-5f);
        s_sh = s;
        g_sw[o] = s;
    }
    __syncthreads();
    const float inv_s = 1.0f / s_sh;

    uint32_t p[8];
#pragma unroll
    for (int i = 0; i < 8; ++i) {
        float t0 = fminf(fmaxf(rintf(v[2*i+0] * inv_s), -1.f), 1.f);
        float t1 = fminf(fmaxf(rintf(v[2*i+1] * inv_s), -1.f), 1.f);
        __half2 h = __floats2half2_rn(t0, t1);
        p[i] = *reinterpret_cast<uint32_t*>(&h);
    }

    uint4* dst = reinterpret_cast<uint4*>(g_wt + (size_t)o * K_TOT + t * 16);
    dst[0] = make_uint4(p[0], p[1], p[2], p[3]);
    dst[1] = make_uint4(p[4], p[5], p[6], p[7]);
}

// ---------------------------------------------------------------------------
// GEMM: 128M x 256N per CTA, K-step 32, 4-stage cp.async pipeline, mma.sync.
// 8 warps (2M x 4N), each computes 64x64.
// smem swizzle: within a 64B row (4 x 16B chunks), phys_chunk = c ^ ((row>>1)&3)
//   -> 8-row ldmatrix phases touch 8 distinct 16B granules (conflict-free).
// ---------------------------------------------------------------------------
__global__ void __launch_bounds__(256, 1) bitlinear_gemm(float* __restrict__ out) {
    extern __shared__ __align__(128) unsigned char smem[];
    __shared__ float s_sw[TILE_N];
    const uint32_t sb = smem_u32(smem);
    const int tid  = threadIdx.x;
    const int lane = tid & 31;
    const int wid  = tid >> 5;
    const int nt = blockIdx.x;   // 0..15
    const int mt = blockIdx.y;   // 0..63
    const int warp_m = (wid & 1) * 64;
    const int warp_n = (wid >> 1) * 64;

    s_sw[tid] = g_sw[nt * TILE_N + tid];

    const __half* gA = g_z  + (size_t)(mt * TILE_M) * K_TOT;
    const __half* gB = g_wt + (size_t)(nt * TILE_N) * K_TOT;

    // --- loader task precompute (A: 512 x 16B chunks, B: 1024) ---
    uint32_t a_sm[2]; const __half* a_gm[2];
#pragma unroll
    for (int i = 0; i < 2; ++i) {
        int idx = tid + 256 * i, r = idx >> 2, c = idx & 3;
        a_sm[i] = r * 64 + ((c ^ ((r >> 1) & 3)) * 16);
        a_gm[i] = gA + (size_t)r * K_TOT + c * 8;
    }
    uint32_t b_sm[4]; const __half* b_gm[4];
#pragma unroll
    for (int i = 0; i < 4; ++i) {
        int idx = tid + 256 * i, r = idx >> 2, c = idx & 3;
        b_sm[i] = A_STAGE + r * 64 + ((c ^ ((r >> 1) & 3)) * 16);
        b_gm[i] = gB + (size_t)r * K_TOT + c * 8;
    }

    // --- ldmatrix lane address offsets (kk=0); kk=1 -> XOR 32 ---
    const int rA = warp_m + (lane & 15);
    const uint32_t aoff = rA * 64 + ((((lane >> 4) & 1) ^ ((rA >> 1) & 3)) * 16);
    const int rB = warp_n + (lane & 7) + ((lane >> 4) << 3);
    const uint32_t boff = A_STAGE + rB * 64 + ((((lane >> 3) & 1) ^ ((rB >> 1) & 3)) * 16);

    float acc[4][8][4];
#pragma unroll
    for (int i = 0; i < 4; ++i)
#pragma unroll
        for (int j = 0; j < 8; ++j)
#pragma unroll
            for (int e = 0; e < 4; ++e) acc[i][j][e] = 0.f;

    // prologue: prefetch 3 k-tiles
#pragma unroll
    for (int s = 0; s < STAGES - 1; ++s) {
        uint32_t base = sb + s * STAGE_BYTES;
#pragma unroll
        for (int i = 0; i < 2; ++i) cp_async16(base + a_sm[i], a_gm[i] + s * TILE_K);
#pragma unroll
        for (int i = 0; i < 4; ++i) cp_async16(base + b_sm[i], b_gm[i] + s * TILE_K);
        cp_commit();
    }

    for (int kt = 0; kt < NK; ++kt) {
        cp_wait<STAGES - 2>();
        __syncthreads();

        const uint32_t sbase = sb + (kt & (STAGES - 1)) * STAGE_BYTES;
#pragma unroll
        for (int kk = 0; kk < 2; ++kk) {
            const uint32_t kx = kk << 5;
            uint32_t a[4][4], b[4][4];
#pragma unroll
            for (int i = 0; i < 4; ++i) ldsm4(a[i], (sbase + aoff + i * 1024) ^ kx);
#pragma unroll
            for (int j = 0; j < 4; ++j) ldsm4(b[j], (sbase + boff + j * 1024) ^ kx);
#pragma unroll
            for (int i = 0; i < 4; ++i)
#pragma unroll
                for (int j = 0; j < 8; ++j) {
                    const uint32_t* bt = b[j >> 1];
                    mma16816(acc[i][j], a[i], bt[(j & 1) * 2], bt[(j & 1) * 2 + 1]);
                }
        }

        // prefetch k-tile kt+3 into stage (kt+3)%4 (fully consumed at kt-1;
        // the __syncthreads above makes that visible to all threads)
        if (kt + STAGES - 1 < NK) {
            const int kn = kt + STAGES - 1;
            uint32_t base = sb + (kn & (STAGES - 1)) * STAGE_BYTES;
#pragma unroll
            for (int i = 0; i < 2; ++i) cp_async16(base + a_sm[i], a_gm[i] + kn * TILE_K);
#pragma unroll
            for (int i = 0; i < 4; ++i) cp_async16(base + b_sm[i], b_gm[i] + kn * TILE_K);
        }
        cp_commit();
    }

    // --- epilogue: scale by s_w[n], write fp32 (evict-first stores) ---
#pragma unroll
    for (int i = 0; i < 4; ++i) {
        const int r0 = mt * TILE_M + warp_m + i * 16 + (lane >> 2);
        float* o0 = out + (size_t)r0 * N_TOT + nt * TILE_N;
        float* o1 = o0 + 8 * N_TOT;
#pragma unroll
        for (int j = 0; j < 8; ++j) {
            const int col = warp_n + j * 8 + (lane & 3) * 2;
            const float sw0 = s_sw[col], sw1 = s_sw[col + 1];
            float2 v0 = make_float2(acc[i][j][0] * sw0, acc[i][j][1] * sw1);
            float2 v1 = make_float2(acc[i][j][2] * sw0, acc[i][j][3] * sw1);
            __stcs(reinterpret_cast<float2*>(o0 + col), v0);
            __stcs(reinterpret_cast<float2*>(o1 + col), v1);
        }
    }
}

// ---------------------------------------------------------------------------
// launch
// ---------------------------------------------------------------------------
extern "C" void kernel_launch(void* const* d_in, const int* in_sizes, int n_in,
                              void* d_out, int out_size) {
    (void)in_sizes; (void)n_in; (void)out_size;
    const float* x = (const float*)d_in[0];   // [4,2048,4096] fp32
    const float* w = (const float*)d_in[1];   // [4096,4096]   fp32
    float* out = (float*)d_out;               // [4,2048,4096] fp32

    quant_x_kernel<<<M_TOT, 256>>>(x);
    quant_w_kernel<<<N_TOT, 256>>>(w);

    static bool attr_set = false;
    if (!attr_set) {
        cudaFuncSetAttribute(bitlinear_gemm,
                             cudaFuncAttributeMaxDynamicSharedMemorySize, SMEM_DYN);
        attr_set = true;
    }
    dim3 grid(N_TOT / TILE_N, M_TOT / TILE_M);   // (16, 64)
    bitlinear_gemm<<<grid, 256, SMEM_DYN>>>(out);
}

// round 16
// speedup vs baseline: 1.1226x; 1.0054x over previous
#include <cuda_runtime.h>
#include <cuda_fp16.h>
#include <cstdint>

// ---------------------------------------------------------------------------
// BitLinear 1.58b on sm_103 (baseline PTX only — no tcgen05 / 'a' features):
//   y[m,o] = s_w[o] * sum_k z[m,k] * t[o,k]
//   z = absmax fake-quant of x (fp16), t = ternary weights {-1,0,1} (fp16)
// r11-exact GEMM (641.8us validated). Deltas this round (quant phase only):
//   1) quant_x and quant_w run CONCURRENTLY via capture-legal event fork
//   2) read-once inputs x,w loaded with __ldcs (evict-first; preserves the
//      freshly written g_z/g_wt lines in L2 for the GEMM)
// ---------------------------------------------------------------------------

static constexpr int M_TOT = 8192;
static constexpr int K_TOT = 4096;
static constexpr int N_TOT = 4096;

static constexpr int TILE_M = 128;
static constexpr int TILE_N = 256;
static constexpr int TILE_K = 32;
static constexpr int NK     = K_TOT / TILE_K;   // 128
static constexpr int STAGES = 4;

static constexpr int A_STAGE = TILE_M * TILE_K * 2;      // 8192 B
static constexpr int B_STAGE = TILE_N * TILE_K * 2;      // 16384 B
static constexpr int STAGE_BYTES = A_STAGE + B_STAGE;    // 24576 B
static constexpr int SMEM_DYN = STAGES * STAGE_BYTES;    // 98304 B

// scratch: quantized operands (module-scope device memory, no allocs)
__device__ __align__(16) __half g_z [(size_t)M_TOT * K_TOT];   // 64 MB
__device__ __align__(16) __half g_wt[(size_t)N_TOT * K_TOT];   // 32 MB
__device__ float g_sw[N_TOT];

// ---------------------------------------------------------------------------
// PTX helpers (all baseline sm_80/sm_90 features)
// ---------------------------------------------------------------------------
__device__ __forceinline__ uint32_t smem_u32(const void* p) {
    uint32_t a;
    asm("{ .reg .u64 t; cvta.to.shared.u64 t, %1; cvt.u32.u64 %0, t; }" : "=r"(a) : "l"(p));
    return a;
}
__device__ __forceinline__ void cp_async16(uint32_t saddr, const void* g) {
    asm volatile("cp.async.cg.shared.global [%0], [%1], 16;" :: "r"(saddr), "l"(g) : "memory");
}
__device__ __forceinline__ void cp_commit() {
    asm volatile("cp.async.commit_group;" ::: "memory");
}
template<int N> __device__ __forceinline__ void cp_wait() {
    asm volatile("cp.async.wait_group %0;" :: "n"(N) : "memory");
}
__device__ __forceinline__ void ldsm4(uint32_t* r, uint32_t addr) {
    asm volatile("ldmatrix.sync.aligned.m8n8.x4.shared.b16 {%0,%1,%2,%3}, [%4];"
                 : "=r"(r[0]), "=r"(r[1]), "=r"(r[2]), "=r"(r[3]) : "r"(addr));
}
__device__ __forceinline__ void mma16816(float* c, const uint32_t* a, uint32_t b0, uint32_t b1) {
    asm volatile(
        "mma.sync.aligned.m16n8k16.row.col.f32.f16.f16.f32 "
        "{%0,%1,%2,%3}, {%4,%5,%6,%7}, {%8,%9}, {%0,%1,%2,%3};"
        : "+f"(c[0]), "+f"(c[1]), "+f"(c[2]), "+f"(c[3])
        : "r"(a[0]), "r"(a[1]), "r"(a[2]), "r"(a[3]), "r"(b0), "r"(b1));
}
// evict-first 16B load (read-once streams)
__device__ __forceinline__ float4 ldcs4(const float4* p) {
    float4 v;
    asm volatile("ld.global.cs.v4.f32 {%0,%1,%2,%3}, [%4];"
                 : "=f"(v.x), "=f"(v.y), "=f"(v.z), "=f"(v.w) : "l"(p));
    return v;
}

// ---------------------------------------------------------------------------
// quantize x: per-token groups of 64, absmax fake-quant -> fp16 row-major
// grid = 8192 blocks x 256 threads; thread t handles 16 contiguous k
// ---------------------------------------------------------------------------
__global__ void __launch_bounds__(256) quant_x_kernel(const float* __restrict__ x) {
    const int m = blockIdx.x;
    const int t = threadIdx.x;

    const float4* xp = reinterpret_cast<const float4*>(x + (size_t)m * K_TOT + t * 16);
    float v[16];
#pragma unroll
    for (int i = 0; i < 4; ++i) {
        float4 f = ldcs4(xp + i);
        v[4*i+0] = f.x; v[4*i+1] = f.y; v[4*i+2] = f.z; v[4*i+3] = f.w;
    }

    float am = 0.f;
#pragma unroll
    for (int i = 0; i < 16; ++i) am = fmaxf(am, fabsf(v[i]));
    // group of 64 elems = 4 consecutive lanes (quad-aligned)
    am = fmaxf(am, __shfl_xor_sync(0xffffffffu, am, 1));
    am = fmaxf(am, __shfl_xor_sync(0xffffffffu, am, 2));
    am = fmaxf(am, 1e-5f);
    const float scale = 127.0f / am;
    const float inv   = am * (1.0f / 127.0f);

    uint32_t p[8];
#pragma unroll
    for (int i = 0; i < 8; ++i) {
        float q0 = fminf(fmaxf(rintf(v[2*i+0] * scale), -127.f), 127.f) * inv;
        float q1 = fminf(fmaxf(rintf(v[2*i+1] * scale), -127.f), 127.f) * inv;
        __half2 h = __floats2half2_rn(q0, q1);
        p[i] = *reinterpret_cast<uint32_t*>(&h);
    }

    uint4* dst = reinterpret_cast<uint4*>(g_z + (size_t)m * K_TOT + t * 16);
    dst[0] = make_uint4(p[0], p[1], p[2], p[3]);
    dst[1] = make_uint4(p[4], p[5], p[6], p[7]);
}

// ---------------------------------------------------------------------------
// quantize w: per-row absmean ternary -> fp16 {-1,0,1} row-major; s_w fp32
// ---------------------------------------------------------------------------
__global__ void __launch_bounds__(256) quant_w_kernel(const float* __restrict__ w) {
    __shared__ float red[8];
    __shared__ float s_sh;
    const int o = blockIdx.x;
    const int t = threadIdx.x;

    const float4* wp = reinterpret_cast<const float4*>(w + (size_t)o * K_TOT + t * 16);
    float v[16];
#pragma unroll
    for (int i = 0; i < 4; ++i) {
        float4 f = ldcs4(wp + i);
        v[4*i+0] = f.x; v[4*i+1] = f.y; v[4*i+2] = f.z; v[4*i+3] = f.w;
    }

    float acc = 0.f;
#pragma unroll
    for (int i = 0; i < 16; ++i) acc += fabsf(v[i]);
#pragma unroll
    for (int d = 16; d > 0; d >>= 1) acc += __shfl_xor_sync(0xffffffffu, acc, d);
    if ((t & 31) == 0) red[t >> 5] = acc;
    __syncthreads();
    if (t == 0) {
        float tot = 0.f;
#pragma unroll
        for (int i = 0; i < 8; ++i) tot += red[i];
        float s = fmaxf(tot * (1.0f / 4096.0f), 1e-5f);
        s_sh = s;
        g_sw[o] = s;
    }
    __syncthreads();
    const float inv_s = 1.0f / s_sh;

    uint32_t p[8];
#pragma unroll
    for (int i = 0; i < 8; ++i) {
        float t0 = fminf(fmaxf(rintf(v[2*i+0] * inv_s), -1.f), 1.f);
        float t1 = fminf(fmaxf(rintf(v[2*i+1] * inv_s), -1.f), 1.f);
        __half2 h = __floats2half2_rn(t0, t1);
        p[i] = *reinterpret_cast<uint32_t*>(&h);
    }

    uint4* dst = reinterpret_cast<uint4*>(g_wt + (size_t)o * K_TOT + t * 16);
    dst[0] = make_uint4(p[0], p[1], p[2], p[3]);
    dst[1] = make_uint4(p[4], p[5], p[6], p[7]);
}

// ---------------------------------------------------------------------------
// GEMM (r11 byte-identical, 641.8us validated): 128M x 256N per CTA, K-step 32,
// 4-stage cp.async pipeline, mma.sync. 8 warps (2M x 4N), each 64x64.
// smem swizzle: within a 64B row (4 x 16B chunks), phys_chunk = c ^ ((row>>1)&3)
// ---------------------------------------------------------------------------
__global__ void __launch_bounds__(256, 1) bitlinear_gemm(float* __restrict__ out) {
    extern __shared__ __align__(128) unsigned char smem[];
    __shared__ float s_sw[TILE_N];
    const uint32_t sb = smem_u32(smem);
    const int tid  = threadIdx.x;
    const int lane = tid & 31;
    const int wid  = tid >> 5;
    const int nt = blockIdx.x;   // 0..15
    const int mt = blockIdx.y;   // 0..63
    const int warp_m = (wid & 1) * 64;
    const int warp_n = (wid >> 1) * 64;

    s_sw[tid] = g_sw[nt * TILE_N + tid];

    const __half* gA = g_z  + (size_t)(mt * TILE_M) * K_TOT;
    const __half* gB = g_wt + (size_t)(nt * TILE_N) * K_TOT;

    // --- loader task precompute (A: 512 x 16B chunks, B: 1024) ---
    uint32_t a_sm[2]; const __half* a_gm[2];
#pragma unroll
    for (int i = 0; i < 2; ++i) {
        int idx = tid + 256 * i, r = idx >> 2, c = idx & 3;
        a_sm[i] = r * 64 + ((c ^ ((r >> 1) & 3)) * 16);
        a_gm[i] = gA + (size_t)r * K_TOT + c * 8;
    }
    uint32_t b_sm[4]; const __half* b_gm[4];
#pragma unroll
    for (int i = 0; i < 4; ++i) {
        int idx = tid + 256 * i, r = idx >> 2, c = idx & 3;
        b_sm[i] = A_STAGE + r * 64 + ((c ^ ((r >> 1) & 3)) * 16);
        b_gm[i] = gB + (size_t)r * K_TOT + c * 8;
    }

    // --- ldmatrix lane address offsets (kk=0); kk=1 -> XOR 32 ---
    const int rA = warp_m + (lane & 15);
    const uint32_t aoff = rA * 64 + ((((lane >> 4) & 1) ^ ((rA >> 1) & 3)) * 16);
    const int rB = warp_n + (lane & 7) + ((lane >> 4) << 3);
    const uint32_t boff = A_STAGE + rB * 64 + ((((lane >> 3) & 1) ^ ((rB >> 1) & 3)) * 16);

    float acc[4][8][4];
#pragma unroll
    for (int i = 0; i < 4; ++i)
#pragma unroll
        for (int j = 0; j < 8; ++j)
#pragma unroll
            for (int e = 0; e < 4; ++e) acc[i][j][e] = 0.f;

    // prologue: prefetch 3 k-tiles
#pragma unroll
    for (int s = 0; s < STAGES - 1; ++s) {
        uint32_t base = sb + s * STAGE_BYTES;
#pragma unroll
        for (int i = 0; i < 2; ++i) cp_async16(base + a_sm[i], a_gm[i] + s * TILE_K);
#pragma unroll
        for (int i = 0; i < 4; ++i) cp_async16(base + b_sm[i], b_gm[i] + s * TILE_K);
        cp_commit();
    }

    for (int kt = 0; kt < NK; ++kt) {
        cp_wait<STAGES - 2>();
        __syncthreads();

        const uint32_t sbase = sb + (kt & (STAGES - 1)) * STAGE_BYTES;
#pragma unroll
        for (int kk = 0; kk < 2; ++kk) {
            const uint32_t kx = kk << 5;
            uint32_t a[4][4], b[4][4];
#pragma unroll
            for (int i = 0; i < 4; ++i) ldsm4(a[i], (sbase + aoff + i * 1024) ^ kx);
#pragma unroll
            for (int j = 0; j < 4; ++j) ldsm4(b[j], (sbase + boff + j * 1024) ^ kx);
#pragma unroll
            for (int i = 0; i < 4; ++i)
#pragma unroll
                for (int j = 0; j < 8; ++j) {
                    const uint32_t* bt = b[j >> 1];
                    mma16816(acc[i][j], a[i], bt[(j & 1) * 2], bt[(j & 1) * 2 + 1]);
                }
        }

        // prefetch k-tile kt+3 into stage (kt+3)%4 (fully consumed at kt-1;
        // the __syncthreads above makes that visible to all threads)
        if (kt + STAGES - 1 < NK) {
            const int kn = kt + STAGES - 1;
            uint32_t base = sb + (kn & (STAGES - 1)) * STAGE_BYTES;
#pragma unroll
            for (int i = 0; i < 2; ++i) cp_async16(base + a_sm[i], a_gm[i] + kn * TILE_K);
#pragma unroll
            for (int i = 0; i < 4; ++i) cp_async16(base + b_sm[i], b_gm[i] + kn * TILE_K);
        }
        cp_commit();
    }

    // --- epilogue: scale by s_w[n], write fp32 ---
#pragma unroll
    for (int i = 0; i < 4; ++i) {
        const int r0 = mt * TILE_M + warp_m + i * 16 + (lane >> 2);
        float* o0 = out + (size_t)r0 * N_TOT + nt * TILE_N;
        float* o1 = o0 + 8 * N_TOT;
#pragma unroll
        for (int j = 0; j < 8; ++j) {
            const int col = warp_n + j * 8 + (lane & 3) * 2;
            const float sw0 = s_sw[col], sw1 = s_sw[col + 1];
            float2 v0 = make_float2(acc[i][j][0] * sw0, acc[i][j][1] * sw1);
            float2 v1 = make_float2(acc[i][j][2] * sw0, acc[i][j][3] * sw1);
            *reinterpret_cast<float2*>(o0 + col) = v0;
            *reinterpret_cast<float2*>(o1 + col) = v1;
        }
    }
}

// ---------------------------------------------------------------------------
// launch: quant_x (main stream) || quant_w (side stream) -> gemm (main stream)
// Event fork/join is the documented capture-legal way to build a parallel
// branch in the captured graph. Stream/events created once on the first
// (uncaptured) correctness call; no device memory is allocated.
// ---------------------------------------------------------------------------
extern "C" void kernel_launch(void* const* d_in, const int* in_sizes, int n_in,
                              void* d_out, int out_size) {
    (void)in_sizes; (void)n_in; (void)out_size;
    const float* x = (const float*)d_in[0];   // [4,2048,4096] fp32
    const float* w = (const float*)d_in[1];   // [4096,4096]   fp32
    float* out = (float*)d_out;               // [4,2048,4096] fp32

    static cudaStream_t s1 = nullptr;
    static cudaEvent_t e_fork = nullptr, e_join = nullptr;
    static bool inited = false;
    if (!inited) {
        cudaStreamCreateWithFlags(&s1, cudaStreamNonBlocking);
        cudaEventCreateWithFlags(&e_fork, cudaEventDisableTiming);
        cudaEventCreateWithFlags(&e_join, cudaEventDisableTiming);
        cudaFuncSetAttribute(bitlinear_gemm,
                             cudaFuncAttributeMaxDynamicSharedMemorySize, SMEM_DYN);
        inited = true;
    }

    // fork: side stream runs quant_w concurrently with quant_x
    cudaEventRecord(e_fork, 0);
    cudaStreamWaitEvent(s1, e_fork, 0);

    quant_x_kernel<<<M_TOT, 256>>>(x);
    quant_w_kernel<<<N_TOT, 256, 0, s1>>>(w);

    // join: gemm waits for quant_w branch
    cudaEventRecord(e_join, s1);
    cudaStreamWaitEvent(0, e_join, 0);

    dim3 grid(N_TOT / TILE_N, M_TOT / TILE_M);   // (16, 64)
    bitlinear_gemm<<<grid, 256, SMEM_DYN>>>(out);
}